// round 1
// baseline (speedup 1.0000x reference)
#include <cuda_runtime.h>
#include <cuda_bf16.h>
#include <cstdint>

// Problem constants (from reference: H=W=256, SMALL=8, LARGE=16, B=2)
#define HW    65536      // H*W
#define NB    2          // batch
#define WNUM  1024       // (H/SMALL)*(W/SMALL)
#define S2    64         // SMALL*SMALL
#define L2    256        // LARGE*LARGE
#define NTILE (WNUM*NB)  // 2048 (w,b) tiles

// Scratch (allocation-free rule: __device__ globals)
__device__ int    g_partner[NB * HW];      // 512 KB, fits L2
__device__ float2 g_partials[NTILE];       // {nll_sum/c_num, absdiff_sum} per tile

// ---------------------------------------------------------------------------
// Kernel A1: zero partner (matches jnp.zeros before scatter)
// ---------------------------------------------------------------------------
__global__ void k_init_partner() {
    int i = blockIdx.x * blockDim.x + threadIdx.x;
    if (i < NB * HW) g_partner[i] = 0;
}

// ---------------------------------------------------------------------------
// Kernel A2: scatter partner[b, idx1[b,j]] = idx0[b,j]
// index_r layout: [B, 2, HW]
// ---------------------------------------------------------------------------
__global__ void k_scatter(const int* __restrict__ index_r) {
    int i = blockIdx.x * blockDim.x + threadIdx.x;
    if (i < NB * HW) {
        int b = i >> 16;          // i / HW
        int j = i & (HW - 1);     // i % HW
        int idx0 = index_r[(b * 2 + 0) * HW + j];
        int idx1 = index_r[(b * 2 + 1) * HW + j];
        g_partner[b * HW + idx1] = idx0;
    }
}

// ---------------------------------------------------------------------------
// Warp reduce helper
// ---------------------------------------------------------------------------
__device__ __forceinline__ float warp_sum(float v) {
    #pragma unroll
    for (int o = 16; o > 0; o >>= 1) v += __shfl_down_sync(0xFFFFFFFFu, v, o);
    return v;
}

// ---------------------------------------------------------------------------
// Kernel B: stream P, fuse M construction + both loss partials.
// One block per (w,b) tile. 256 threads; thread t owns columns l=4*(t&63)..+3
// and rows s = (t>>6), +4, +8, ... (16 float4 loads = 64 elements).
// ---------------------------------------------------------------------------
__global__ __launch_bounds__(256, 8)
void k_main(const float4* __restrict__ P,
            const int*    __restrict__ sw_abs,
            const int*    __restrict__ lw_abs) {
    const int bid = blockIdx.x;          // = w*2 + b  (matches P's [w][b] layout)
    const int w   = bid >> 1;
    const int b   = bid & 1;
    const int tid = threadIdx.x;

    __shared__ int s_sw[S2];
    __shared__ int s_plw[L2];
    __shared__ int s_lw[L2];

    if (tid < S2) s_sw[tid] = sw_abs[w * S2 + tid];
    {
        int lw = lw_abs[w * L2 + tid];
        s_lw[tid]  = lw;
        s_plw[tid] = g_partner[b * HW + lw];
    }
    __syncthreads();

    const int l4 = (tid & 63) << 2;      // column base (0..252 step 4)
    const int s0 = tid >> 6;             // row phase (0..3)

    const int  p0 = s_plw[l4 + 0], p1 = s_plw[l4 + 1];
    const int  p2 = s_plw[l4 + 2], p3 = s_plw[l4 + 3];
    const bool z0 = (s_lw[l4 + 0] == 0), z1 = (s_lw[l4 + 1] == 0);
    const bool z2 = (s_lw[l4 + 2] == 0), z3 = (s_lw[l4 + 3] == 0);

    const float4* Pb = P + (size_t)bid * (S2 * L2 / 4) + (l4 >> 2);

    float absd = 0.f, nll = 0.f;
    int   cnt  = 0;

    #pragma unroll 4
    for (int s = s0; s < S2; s += 4) {
        float4 p = __ldg(Pb + s * (L2 / 4));
        int  sw  = s_sw[s];
        bool swz = (sw == 0);

        bool m0 = (sw == p0) && !(swz && z0);
        bool m1 = (sw == p1) && !(swz && z1);
        bool m2 = (sw == p2) && !(swz && z2);
        bool m3 = (sw == p3) && !(swz && z3);

        absd += fabsf(p.x - (m0 ? 1.f : 0.f));
        absd += fabsf(p.y - (m1 ? 1.f : 0.f));
        absd += fabsf(p.z - (m2 ? 1.f : 0.f));
        absd += fabsf(p.w - (m3 ? 1.f : 0.f));

        if (m0) { nll -= __logf(fminf(fmaxf(p.x, 1e-6f), 1.f - 1e-6f)); cnt++; }
        if (m1) { nll -= __logf(fminf(fmaxf(p.y, 1e-6f), 1.f - 1e-6f)); cnt++; }
        if (m2) { nll -= __logf(fminf(fmaxf(p.z, 1e-6f), 1.f - 1e-6f)); cnt++; }
        if (m3) { nll -= __logf(fminf(fmaxf(p.w, 1e-6f), 1.f - 1e-6f)); cnt++; }
    }

    // Block reduction (deterministic tree)
    float cntf = (float)cnt;
    absd = warp_sum(absd);
    nll  = warp_sum(nll);
    cntf = warp_sum(cntf);

    __shared__ float red[3][8];
    int lane = tid & 31, wrp = tid >> 5;
    if (lane == 0) { red[0][wrp] = absd; red[1][wrp] = nll; red[2][wrp] = cntf; }
    __syncthreads();

    if (wrp == 0) {
        float a = (lane < 8) ? red[0][lane] : 0.f;
        float n = (lane < 8) ? red[1][lane] : 0.f;
        float c = (lane < 8) ? red[2][lane] : 0.f;
        #pragma unroll
        for (int o = 4; o > 0; o >>= 1) {
            a += __shfl_down_sync(0xFFFFFFFFu, a, o);
            n += __shfl_down_sync(0xFFFFFFFFu, n, o);
            c += __shfl_down_sync(0xFFFFFFFFu, c, o);
        }
        if (lane == 0) g_partials[bid] = make_float2(n / c, a);
    }
}

// ---------------------------------------------------------------------------
// Kernel C: final deterministic reduction of 2048 partials -> two scalars
// ---------------------------------------------------------------------------
__global__ void k_final(float* __restrict__ out) {
    const int tid = threadIdx.x;  // 1024 threads
    float r = 0.f, a = 0.f;
    #pragma unroll
    for (int i = tid; i < NTILE; i += 1024) {
        float2 v = g_partials[i];
        r += v.x; a += v.y;
    }
    r = warp_sum(r);
    a = warp_sum(a);

    __shared__ float sr[32], sa[32];
    int lane = tid & 31, wrp = tid >> 5;
    if (lane == 0) { sr[wrp] = r; sa[wrp] = a; }
    __syncthreads();
    if (wrp == 0) {
        r = sr[lane];
        a = sa[lane];
        r = warp_sum(r);
        a = warp_sum(a);
        if (lane == 0) {
            out[0] = r / (float)NTILE;                         // l_cm
            out[1] = a / (float)((size_t)NTILE * S2 * L2);     // l_c  (/33554432)
        }
    }
}

// ---------------------------------------------------------------------------
// Launch
// Inputs (metadata order): [0] correspondence_matrixs f32, [1] index_r i32,
//                          [2] sw_abs i32, [3] lw_abs i32. Output: 2 f32.
// ---------------------------------------------------------------------------
extern "C" void kernel_launch(void* const* d_in, const int* in_sizes, int n_in,
                              void* d_out, int out_size) {
    const float4* P      = (const float4*)d_in[0];
    const int*    idxr   = (const int*)d_in[1];
    const int*    sw_abs = (const int*)d_in[2];
    const int*    lw_abs = (const int*)d_in[3];
    float*        out    = (float*)d_out;

    k_init_partner<<<(NB * HW + 255) / 256, 256>>>();
    k_scatter<<<(NB * HW + 255) / 256, 256>>>(idxr);
    k_main<<<NTILE, 256>>>(P, sw_abs, lw_abs);
    k_final<<<1, 1024>>>(out);
}

// round 2
// speedup vs baseline: 1.0538x; 1.0538x over previous
#include <cuda_runtime.h>
#include <cuda_bf16.h>
#include <cstdint>

// Problem constants (H=W=256, SMALL=8, LARGE=16, B=2)
#define HW    65536
#define NB    2
#define WNUM  1024
#define S2    64
#define L2    256
#define NTILE (WNUM*NB)   // 2048

__device__ int    g_partner[NB * HW];   // 512 KB
__device__ float2 g_partials[NTILE];    // 16 KB
__device__ int    g_ticket;             // zero-initialized; last block resets it

// ---------------------------------------------------------------------------
// Kernel A: scatter partner[b, idx1[b,j]] = idx0[b,j].
// idx1[b,:] is a permutation of [0,HW) (reference setup), so every cell of
// g_partner is overwritten each launch -> no zero-init pass needed and each
// graph replay is deterministic.
// ---------------------------------------------------------------------------
__global__ void k_scatter(const int* __restrict__ index_r) {
    int i = blockIdx.x * blockDim.x + threadIdx.x;   // grid covers NB*HW exactly
    int b = i >> 16;
    int j = i & (HW - 1);
    int idx0 = index_r[(b * 2 + 0) * HW + j];
    int idx1 = index_r[(b * 2 + 1) * HW + j];
    g_partner[b * HW + idx1] = idx0;
}

__device__ __forceinline__ float warp_sum(float v) {
    #pragma unroll
    for (int o = 16; o > 0; o >>= 1) v += __shfl_down_sync(0xFFFFFFFFu, v, o);
    return v;
}

// ---------------------------------------------------------------------------
// Kernel B: stream P once; fused M construction + both loss partials;
// last block performs the final reduction (no separate k_final launch).
// One block per (w,b) tile: 256 threads, thread owns 4 columns x 16 rows.
// ---------------------------------------------------------------------------
__global__ __launch_bounds__(256, 8)
void k_main(const float4* __restrict__ P,
            const int*    __restrict__ sw_abs,
            const int*    __restrict__ lw_abs,
            float*        __restrict__ out) {
    const int bid = blockIdx.x;      // = w*2 + b (matches P layout [w][b][s][l])
    const int w   = bid >> 1;
    const int b   = bid & 1;
    const int tid = threadIdx.x;

    __shared__ int s_sw[S2];
    __shared__ int s_plw[L2];
    __shared__ int s_lw[L2];

    if (tid < S2) s_sw[tid] = sw_abs[w * S2 + tid];
    {
        int lw = lw_abs[w * L2 + tid];
        s_lw[tid]  = lw;
        s_plw[tid] = g_partner[b * HW + lw];
    }
    __syncthreads();

    const int l4 = (tid & 63) << 2;   // column base 0..252
    const int s0 = tid >> 6;          // row phase 0..3

    const int  p0 = s_plw[l4 + 0], p1 = s_plw[l4 + 1];
    const int  p2 = s_plw[l4 + 2], p3 = s_plw[l4 + 3];
    const bool z0 = (s_lw[l4 + 0] == 0), z1 = (s_lw[l4 + 1] == 0);
    const bool z2 = (s_lw[l4 + 2] == 0), z3 = (s_lw[l4 + 3] == 0);

    const float4* Pb = P + (size_t)bid * (S2 * L2 / 4) + (l4 >> 2);

    float absd = 0.f, nll = 0.f;
    int   cnt  = 0;

    #pragma unroll 4
    for (int s = s0; s < S2; s += 4) {
        float4 p = __ldcs(Pb + s * (L2 / 4));   // streaming: read-once data
        int  sw  = s_sw[s];
        bool swz = (sw == 0);

        bool m0 = (sw == p0) && !(swz && z0);
        bool m1 = (sw == p1) && !(swz && z1);
        bool m2 = (sw == p2) && !(swz && z2);
        bool m3 = (sw == p3) && !(swz && z3);

        absd += fabsf(p.x - (m0 ? 1.f : 0.f));
        absd += fabsf(p.y - (m1 ? 1.f : 0.f));
        absd += fabsf(p.z - (m2 ? 1.f : 0.f));
        absd += fabsf(p.w - (m3 ? 1.f : 0.f));

        if (m0) { nll -= __logf(fminf(fmaxf(p.x, 1e-6f), 1.f - 1e-6f)); cnt++; }
        if (m1) { nll -= __logf(fminf(fmaxf(p.y, 1e-6f), 1.f - 1e-6f)); cnt++; }
        if (m2) { nll -= __logf(fminf(fmaxf(p.z, 1e-6f), 1.f - 1e-6f)); cnt++; }
        if (m3) { nll -= __logf(fminf(fmaxf(p.w, 1e-6f), 1.f - 1e-6f)); cnt++; }
    }

    // Per-block deterministic tree reduction
    float cntf = (float)cnt;
    absd = warp_sum(absd);
    nll  = warp_sum(nll);
    cntf = warp_sum(cntf);

    __shared__ float red[3][8];
    __shared__ bool  s_last;
    const int lane = tid & 31, wrp = tid >> 5;
    if (lane == 0) { red[0][wrp] = absd; red[1][wrp] = nll; red[2][wrp] = cntf; }
    __syncthreads();

    if (wrp == 0) {
        float a = (lane < 8) ? red[0][lane] : 0.f;
        float n = (lane < 8) ? red[1][lane] : 0.f;
        float c = (lane < 8) ? red[2][lane] : 0.f;
        #pragma unroll
        for (int o = 4; o > 0; o >>= 1) {
            a += __shfl_down_sync(0xFFFFFFFFu, a, o);
            n += __shfl_down_sync(0xFFFFFFFFu, n, o);
            c += __shfl_down_sync(0xFFFFFFFFu, c, o);
        }
        if (lane == 0) {
            g_partials[bid] = make_float2(n / c, a);
            __threadfence();
            int t = atomicAdd(&g_ticket, 1);
            s_last = (t == NTILE - 1);
        }
    }
    __syncthreads();

    // Last block: reduce all 2048 partials (fixed order -> bit-deterministic)
    if (s_last) {
        float r = 0.f, a = 0.f;
        #pragma unroll
        for (int i = tid; i < NTILE; i += 256) {
            float2 v = g_partials[i];
            r += v.x; a += v.y;
        }
        r = warp_sum(r);
        a = warp_sum(a);
        __shared__ float sr[8], sa[8];
        if (lane == 0) { sr[wrp] = r; sa[wrp] = a; }
        __syncthreads();
        if (wrp == 0) {
            r = (lane < 8) ? sr[lane] : 0.f;
            a = (lane < 8) ? sa[lane] : 0.f;
            #pragma unroll
            for (int o = 4; o > 0; o >>= 1) {
                r += __shfl_down_sync(0xFFFFFFFFu, r, o);
                a += __shfl_down_sync(0xFFFFFFFFu, a, o);
            }
            if (lane == 0) {
                out[0] = r / (float)NTILE;                       // l_cm
                out[1] = a / (float)((size_t)NTILE * S2 * L2);   // l_c
                g_ticket = 0;                                    // rearm for next replay
            }
        }
    }
}

// ---------------------------------------------------------------------------
// Launch.  Inputs: [0] P f32, [1] index_r i32, [2] sw_abs i32, [3] lw_abs i32.
// ---------------------------------------------------------------------------
extern "C" void kernel_launch(void* const* d_in, const int* in_sizes, int n_in,
                              void* d_out, int out_size) {
    const float4* P      = (const float4*)d_in[0];
    const int*    idxr   = (const int*)d_in[1];
    const int*    sw_abs = (const int*)d_in[2];
    const int*    lw_abs = (const int*)d_in[3];
    float*        out    = (float*)d_out;

    k_scatter<<<NB * HW / 256, 256>>>(idxr);
    k_main<<<NTILE, 256>>>(P, sw_abs, lw_abs, out);
}

// round 3
// speedup vs baseline: 1.1854x; 1.1249x over previous
#include <cuda_runtime.h>
#include <cuda_bf16.h>
#include <cstdint>

// Problem constants (H=W=256, SMALL=8, LARGE=16, B=2)
#define HW    65536
#define NB    2
#define WNUM  1024
#define S2    64
#define L2    256
#define NTILE (WNUM*NB)   // 2048

__device__ int    g_partner[NB * HW];   // 512 KB
__device__ float2 g_partials[NTILE];    // 16 KB
__device__ int    g_ticket;             // zero-init; last block resets

// ---------------------------------------------------------------------------
// Kernel A: scatter partner[b, idx1[b,j]] = idx0[b,j].
// idx1[b,:] is a permutation of [0,HW), so every cell is overwritten each
// launch -> no zero-init needed, replays deterministic.
// ---------------------------------------------------------------------------
__global__ void k_scatter(const int* __restrict__ index_r) {
    int i = blockIdx.x * blockDim.x + threadIdx.x;
    int b = i >> 16;
    int j = i & (HW - 1);
    int idx0 = index_r[(b * 2 + 0) * HW + j];
    int idx1 = index_r[(b * 2 + 1) * HW + j];
    g_partner[b * HW + idx1] = idx0;
}

__device__ __forceinline__ float warp_sum(float v) {
    #pragma unroll
    for (int o = 16; o > 0; o >>= 1) v += __shfl_down_sync(0xFFFFFFFFu, v, o);
    return v;
}

// ---------------------------------------------------------------------------
// Kernel B.
// Key identities:
//   |P - M| summed = sum(P) + sum_over_matches(1 - 2P)   (since 0 <= P < 1)
//   sw_abs[w] is the 8x8 pixel block at (r0,c0)=((w>>5)*8,(w&31)*8), value
//   (r0+i)*256+(c0+j) at s=i*8+j  =>  O(1) membership test for plw values.
// Main loop: pure float4 stream + adds. Matches (~64/tile) handled by the 64
// phase-0 threads (4 columns each, fixed order) with scalar re-loads.
// ---------------------------------------------------------------------------
__global__ __launch_bounds__(256, 6)
void k_main(const float4* __restrict__ P,
            const int*    __restrict__ lw_abs,
            float*        __restrict__ out) {
    const int bid = blockIdx.x;      // = w*2 + b  (P layout [w][b][s][l])
    const int w   = bid >> 1;
    const int b   = bid & 1;
    const int tid = threadIdx.x;

    const int l4 = (tid & 63) << 2;  // column base 0..252
    const int s0 = tid >> 6;         // row phase 0..3

    // ---- bulk stream: sum of P over this thread's 4 cols x 16 rows ----
    const float4* Pb = P + (size_t)bid * (S2 * L2 / 4) + (l4 >> 2);
    float a0 = 0.f, a1 = 0.f;
    #pragma unroll
    for (int k = 0; k < 16; k++) {
        float4 p = __ldcs(Pb + (s0 + 4 * k) * (L2 / 4));
        a0 += p.x + p.y;
        a1 += p.z + p.w;
    }
    float absd = a0 + a1;
    float nll  = 0.f;
    int   cnt  = 0;

    // ---- match corrections: phase-0 threads own all 64 rows of their cols ----
    if (tid < 64) {
        const int r0 = (w >> 5) << 3;
        const int c0 = (w & 31) << 3;
        const float* Pf = (const float*)P + (size_t)bid * (S2 * L2);
        #pragma unroll
        for (int c = 0; c < 4; c++) {
            int l  = l4 + c;
            int lw = __ldg(lw_abs + w * L2 + l);
            int v  = g_partner[b * HW + lw];        // plw
            int i  = (v >> 8) - r0;
            int j  = (v & 255) - c0;
            if ((unsigned)i < 8u && (unsigned)j < 8u) {       // v in sw set
                if (!(v == 0 && lw == 0)) {                    // zmask
                    int s   = i * 8 + j;
                    float p = __ldg(Pf + s * L2 + l);
                    absd += 1.f - 2.f * p;                     // |p-1| - p
                    nll  -= __logf(fminf(fmaxf(p, 1e-6f), 1.f - 1e-6f));
                    cnt++;
                }
            }
        }
    }

    // ---- block reduction (deterministic tree) ----
    float cntf = (float)cnt;
    absd = warp_sum(absd);
    nll  = warp_sum(nll);
    cntf = warp_sum(cntf);

    __shared__ float red[3][8];
    __shared__ bool  s_last;
    const int lane = tid & 31, wrp = tid >> 5;
    if (lane == 0) { red[0][wrp] = absd; red[1][wrp] = nll; red[2][wrp] = cntf; }
    __syncthreads();

    if (wrp == 0) {
        float a = (lane < 8) ? red[0][lane] : 0.f;
        float n = (lane < 8) ? red[1][lane] : 0.f;
        float c = (lane < 8) ? red[2][lane] : 0.f;
        #pragma unroll
        for (int o = 4; o > 0; o >>= 1) {
            a += __shfl_down_sync(0xFFFFFFFFu, a, o);
            n += __shfl_down_sync(0xFFFFFFFFu, n, o);
            c += __shfl_down_sync(0xFFFFFFFFu, c, o);
        }
        if (lane == 0) {
            g_partials[bid] = make_float2(n / c, a);
            __threadfence();
            int t = atomicAdd(&g_ticket, 1);
            s_last = (t == NTILE - 1);
        }
    }
    __syncthreads();

    // ---- last block: final fixed-order reduction ----
    if (s_last) {
        float r = 0.f, a = 0.f;
        #pragma unroll
        for (int i = tid; i < NTILE; i += 256) {
            float2 v = g_partials[i];
            r += v.x; a += v.y;
        }
        r = warp_sum(r);
        a = warp_sum(a);
        __shared__ float sr[8], sa[8];
        if (lane == 0) { sr[wrp] = r; sa[wrp] = a; }
        __syncthreads();
        if (wrp == 0) {
            r = (lane < 8) ? sr[lane] : 0.f;
            a = (lane < 8) ? sa[lane] : 0.f;
            #pragma unroll
            for (int o = 4; o > 0; o >>= 1) {
                r += __shfl_down_sync(0xFFFFFFFFu, r, o);
                a += __shfl_down_sync(0xFFFFFFFFu, a, o);
            }
            if (lane == 0) {
                out[0] = r / (float)NTILE;                       // l_cm
                out[1] = a / (float)((size_t)NTILE * S2 * L2);   // l_c
                g_ticket = 0;                                    // rearm
            }
        }
    }
}

// ---------------------------------------------------------------------------
// Launch.  Inputs: [0] P f32, [1] index_r i32, [2] sw_abs i32, [3] lw_abs i32.
// ---------------------------------------------------------------------------
extern "C" void kernel_launch(void* const* d_in, const int* in_sizes, int n_in,
                              void* d_out, int out_size) {
    const float4* P      = (const float4*)d_in[0];
    const int*    idxr   = (const int*)d_in[1];
    const int*    lw_abs = (const int*)d_in[3];
    float*        out    = (float*)d_out;

    k_scatter<<<NB * HW / 256, 256>>>(idxr);
    k_main<<<NTILE, 256>>>(P, lw_abs, out);
}

// round 4
// speedup vs baseline: 1.2630x; 1.0655x over previous
#include <cuda_runtime.h>
#include <cuda_bf16.h>
#include <cstdint>

// Problem constants (H=W=256, SMALL=8, LARGE=16, B=2)
#define HW      65536
#define NB      2
#define WNUM    1024
#define S2      64
#define L2      256
#define NTILE   (WNUM*NB)       // 2048
#define NELEM4  8388608         // 32M floats / 4
#define NBLK    1024            // bulk grid: 1024*256*32 float4 == NELEM4 exactly

__device__ int    g_partner[NB * HW];   // 512 KB (L2-resident)
__device__ float2 g_corr[NTILE];        // per-tile {nll_sum/c_num, absd_correction}
__device__ float  g_bulk[NBLK];         // per-block bulk sums
__device__ int    g_ticket;             // zero-init; last block resets

// ---------------------------------------------------------------------------
// Kernel A: scatter partner[b, idx1[b,j]] = idx0[b,j].
// idx1[b,:] is a permutation of [0,HW) -> every cell overwritten each launch.
// ---------------------------------------------------------------------------
__global__ void k_scatter(const int* __restrict__ index_r) {
    int i = blockIdx.x * blockDim.x + threadIdx.x;
    int b = i >> 16;
    int j = i & (HW - 1);
    int idx0 = index_r[(b * 2 + 0) * HW + j];
    int idx1 = index_r[(b * 2 + 1) * HW + j];
    g_partner[b * HW + idx1] = idx0;
}

__device__ __forceinline__ float warp_sum(float v) {
    #pragma unroll
    for (int o = 16; o > 0; o >>= 1) v += __shfl_down_sync(0xFFFFFFFFu, v, o);
    return v;
}

// ---------------------------------------------------------------------------
// Kernel B: per-tile match corrections. One warp per tile.
// sw_abs[w] is the 8x8 block at (r0,c0)=((w>>5)*8,(w&31)*8): value
// (r0+i)*256+(c0+j) at s=i*8+j  => O(1) membership test for partner values.
// Per tile: 256 lw loads + 256 partner gathers (L2) + ~64 scattered P loads.
// ---------------------------------------------------------------------------
__global__ __launch_bounds__(256, 8)
void k_corr(const float* __restrict__ P,
            const int*   __restrict__ lw_abs) {
    const int tile = blockIdx.x * 8 + (threadIdx.x >> 5);  // 256 blocks * 8 warps
    const int lane = threadIdx.x & 31;
    const int w    = tile >> 1;
    const int b    = tile & 1;
    const int r0   = (w >> 5) << 3;
    const int c0   = (w & 31) << 3;

    const float* Pf = P + (size_t)tile * (S2 * L2);

    float absd = 0.f, nll = 0.f;
    int   cnt  = 0;

    #pragma unroll
    for (int k = 0; k < 8; k++) {
        int l  = lane + 32 * k;                      // coalesced lw load
        int lw = __ldg(lw_abs + w * L2 + l);
        int v  = g_partner[b * HW + lw];             // plw
        int i  = (v >> 8) - r0;
        int j  = (v & 255) - c0;
        if ((unsigned)i < 8u && (unsigned)j < 8u && !(v == 0 && lw == 0)) {
            int s   = i * 8 + j;
            float p = __ldg(Pf + s * L2 + l);
            absd += 1.f - 2.f * p;                   // |p-1| - p  correction
            nll  -= __logf(fminf(fmaxf(p, 1e-6f), 1.f - 1e-6f));
            cnt++;
        }
    }

    float cntf = (float)cnt;
    absd = warp_sum(absd);
    nll  = warp_sum(nll);
    cntf = warp_sum(cntf);
    if (lane == 0) g_corr[tile] = make_float2(nll / cntf, absd);
}

// ---------------------------------------------------------------------------
// Kernel C: bulk sum of all of P. Single wave: 1024 blocks x 256 threads x
// 32 float4 each == entire array, no remainder. Long per-block loop ->
// per-CTA spread floor (~1.1), no wave quantization.
// Last block folds in g_corr and writes the two outputs.
// ---------------------------------------------------------------------------
__global__ __launch_bounds__(256, 8)
void k_bulk(const float4* __restrict__ P, float* __restrict__ out) {
    const int tid  = threadIdx.x;
    const int base = blockIdx.x * 256 + tid;

    float a0 = 0.f, a1 = 0.f;
    #pragma unroll 8
    for (int k = 0; k < 32; k++) {
        float4 p = __ldcs(P + base + (size_t)k * (NBLK * 256));
        a0 += p.x + p.y;
        a1 += p.z + p.w;
    }
    float acc = a0 + a1;

    acc = warp_sum(acc);
    __shared__ float red[8];
    __shared__ bool  s_last;
    const int lane = tid & 31, wrp = tid >> 5;
    if (lane == 0) red[wrp] = acc;
    __syncthreads();

    if (wrp == 0) {
        float a = (lane < 8) ? red[lane] : 0.f;
        #pragma unroll
        for (int o = 4; o > 0; o >>= 1) a += __shfl_down_sync(0xFFFFFFFFu, a, o);
        if (lane == 0) {
            g_bulk[blockIdx.x] = a;
            __threadfence();
            int t = atomicAdd(&g_ticket, 1);
            s_last = (t == NBLK - 1);
        }
    }
    __syncthreads();

    if (s_last) {
        // fixed-order final reduction: 1024 bulk partials + 2048 corr partials
        float sumP = 0.f, sumC = 0.f, sumR = 0.f;
        #pragma unroll
        for (int i = tid; i < NBLK; i += 256) sumP += g_bulk[i];
        #pragma unroll
        for (int i = tid; i < NTILE; i += 256) {
            float2 v = g_corr[i];
            sumR += v.x;            // nll/c_num per tile
            sumC += v.y;            // absd corrections
        }
        sumP = warp_sum(sumP);
        sumC = warp_sum(sumC);
        sumR = warp_sum(sumR);
        __shared__ float sp[8], sc[8], sr[8];
        if (lane == 0) { sp[wrp] = sumP; sc[wrp] = sumC; sr[wrp] = sumR; }
        __syncthreads();
        if (wrp == 0) {
            float p = (lane < 8) ? sp[lane] : 0.f;
            float c = (lane < 8) ? sc[lane] : 0.f;
            float r = (lane < 8) ? sr[lane] : 0.f;
            #pragma unroll
            for (int o = 4; o > 0; o >>= 1) {
                p += __shfl_down_sync(0xFFFFFFFFu, p, o);
                c += __shfl_down_sync(0xFFFFFFFFu, c, o);
                r += __shfl_down_sync(0xFFFFFFFFu, r, o);
            }
            if (lane == 0) {
                out[0] = r / (float)NTILE;                          // l_cm
                out[1] = (p + c) / (float)((size_t)NTILE * S2 * L2);// l_c
                g_ticket = 0;                                       // rearm
            }
        }
    }
}

// ---------------------------------------------------------------------------
// Launch.  Inputs: [0] P f32, [1] index_r i32, [2] sw_abs i32, [3] lw_abs i32.
// ---------------------------------------------------------------------------
extern "C" void kernel_launch(void* const* d_in, const int* in_sizes, int n_in,
                              void* d_out, int out_size) {
    const float*  Pf     = (const float*)d_in[0];
    const float4* P4     = (const float4*)d_in[0];
    const int*    idxr   = (const int*)d_in[1];
    const int*    lw_abs = (const int*)d_in[3];
    float*        out    = (float*)d_out;

    k_scatter<<<NB * HW / 256, 256>>>(idxr);
    k_corr<<<NTILE / 8, 256>>>(Pf, lw_abs);
    k_bulk<<<NBLK, 256>>>(P4, out);
}

// round 5
// speedup vs baseline: 1.4551x; 1.1521x over previous
#include <cuda_runtime.h>
#include <cuda_bf16.h>
#include <cstdint>

// Problem constants (H=W=256, SMALL=8, LARGE=16, B=2)
#define HW      65536
#define NB      2
#define WNUM    1024
#define S2      64
#define L2      256
#define NTILE   (WNUM*NB)     // 2048
#define NBLK    1024
#define NCORRB  256           // blocks that do scatter+corr
#define K1      14            // bulk iters for corr blocks
#define K2      38            // bulk iters for plain blocks
// 256*256*K1 + 768*256*K2 = 917504 + 7471104 = 8388608 float4 = all of P

__device__ int    g_partner[NB * HW];   // 512 KB (L2-resident)
__device__ float2 g_corr[NTILE];        // {nll_sum/c_num, absd_correction}
__device__ float  g_bulk[NBLK];
__device__ int    g_sync1;              // scatter barrier (zero-init, rearmed)
__device__ int    g_ticket;             // completion ticket (zero-init, rearmed)

__device__ __forceinline__ float warp_sum(float v) {
    #pragma unroll
    for (int o = 16; o > 0; o >>= 1) v += __shfl_down_sync(0xFFFFFFFFu, v, o);
    return v;
}

// ---------------------------------------------------------------------------
// Single fused kernel.
//  blocks 0..255 : scatter slice -> 256-block spin barrier -> per-warp tile
//                  corrections -> K1 bulk iters
//  blocks 256+   : K2 bulk iters immediately (hides scatter/corr latency)
//  last ticket   : fixed-order final combine, writes out, rearms counters
// ---------------------------------------------------------------------------
__global__ __launch_bounds__(256, 6)
void k_all(const float4* __restrict__ P4,
           const float*  __restrict__ Pf,
           const int*    __restrict__ index_r,
           const int*    __restrict__ lw_abs,
           float*        __restrict__ out) {
    const int bid  = blockIdx.x;
    const int tid  = threadIdx.x;
    const int lane = tid & 31;
    const int wrp  = tid >> 5;

    if (bid < NCORRB) {
        // ---- phase 1: scatter (2 entries/thread, coalesced reads) ----
        #pragma unroll
        for (int r = 0; r < 2; r++) {
            int e    = bid * 512 + r * 256 + tid;      // 0..131071
            int b    = e >> 16;
            int j    = e & (HW - 1);
            int idx0 = index_r[(b * 2 + 0) * HW + j];
            int idx1 = index_r[(b * 2 + 1) * HW + j];
            g_partner[b * HW + idx1] = idx0;
        }
        __threadfence();
        __syncthreads();
        // ---- 256-block barrier (all resident in wave 1) ----
        if (tid == 0) {
            atomicAdd(&g_sync1, 1);
            while (*((volatile int*)&g_sync1) < NCORRB) { }
        }
        __syncthreads();
        __threadfence();

        // ---- phase 2: per-warp tile corrections (tile = bid*8 + warp) ----
        const int tile = bid * 8 + wrp;
        const int w    = tile >> 1;
        const int b    = tile & 1;
        const int r0   = (w >> 5) << 3;
        const int c0   = (w & 31) << 3;
        const float* Pt = Pf + (size_t)tile * (S2 * L2);

        float absd = 0.f, nll = 0.f;
        int   cnt  = 0;
        #pragma unroll
        for (int k = 0; k < 8; k++) {
            int l  = lane + 32 * k;
            int lw = __ldg(lw_abs + w * L2 + l);
            int v  = g_partner[b * HW + lw];             // plw
            int i  = (v >> 8) - r0;
            int j  = (v & 255) - c0;
            if ((unsigned)i < 8u && (unsigned)j < 8u && !(v == 0 && lw == 0)) {
                float p = __ldg(Pt + (i * 8 + j) * L2 + l);
                absd += 1.f - 2.f * p;                   // |p-1| - p
                nll  -= __logf(fminf(fmaxf(p, 1e-6f), 1.f - 1e-6f));
                cnt++;
            }
        }
        float cntf = (float)cnt;
        absd = warp_sum(absd);
        nll  = warp_sum(nll);
        cntf = warp_sum(cntf);
        if (lane == 0) g_corr[tile] = make_float2(nll / cntf, absd);
    }

    // ---- phase 3: bulk sum of P (corr blocks: K1 iters; others: K2) ----
    float a0 = 0.f, a1 = 0.f;
    if (bid < NCORRB) {
        const int base = bid * 256 + tid;                // region [0, 917504)
        #pragma unroll
        for (int k = 0; k < K1; k++) {
            float4 p = __ldcs(P4 + base + k * (NCORRB * 256));
            a0 += p.x + p.y;
            a1 += p.z + p.w;
        }
    } else {
        const int base = 917504 + (bid - NCORRB) * 256 + tid;
        #pragma unroll
        for (int k = 0; k < K2; k++) {
            float4 p = __ldcs(P4 + base + k * ((NBLK - NCORRB) * 256));
            a0 += p.x + p.y;
            a1 += p.z + p.w;
        }
    }
    float acc = a0 + a1;

    // ---- block reduction ----
    acc = warp_sum(acc);
    __shared__ float red[8];
    __shared__ bool  s_last;
    if (lane == 0) red[wrp] = acc;
    __syncthreads();
    if (wrp == 0) {
        float a = (lane < 8) ? red[lane] : 0.f;
        #pragma unroll
        for (int o = 4; o > 0; o >>= 1) a += __shfl_down_sync(0xFFFFFFFFu, a, o);
        if (lane == 0) {
            g_bulk[bid] = a;
            __threadfence();
            int t = atomicAdd(&g_ticket, 1);
            s_last = (t == NBLK - 1);
        }
    }
    __syncthreads();

    // ---- final fixed-order combine (deterministic) ----
    if (s_last) {
        float sumP = 0.f, sumC = 0.f, sumR = 0.f;
        #pragma unroll
        for (int i = tid; i < NBLK; i += 256) sumP += g_bulk[i];
        #pragma unroll
        for (int i = tid; i < NTILE; i += 256) {
            float2 v = g_corr[i];
            sumR += v.x;
            sumC += v.y;
        }
        sumP = warp_sum(sumP);
        sumC = warp_sum(sumC);
        sumR = warp_sum(sumR);
        __shared__ float sp[8], sc[8], sr[8];
        if (lane == 0) { sp[wrp] = sumP; sc[wrp] = sumC; sr[wrp] = sumR; }
        __syncthreads();
        if (wrp == 0) {
            float p = (lane < 8) ? sp[lane] : 0.f;
            float c = (lane < 8) ? sc[lane] : 0.f;
            float r = (lane < 8) ? sr[lane] : 0.f;
            #pragma unroll
            for (int o = 4; o > 0; o >>= 1) {
                p += __shfl_down_sync(0xFFFFFFFFu, p, o);
                c += __shfl_down_sync(0xFFFFFFFFu, c, o);
                r += __shfl_down_sync(0xFFFFFFFFu, r, o);
            }
            if (lane == 0) {
                out[0] = r / (float)NTILE;                            // l_cm
                out[1] = (p + c) / (float)((size_t)NTILE * S2 * L2);  // l_c
                g_ticket = 0;                                         // rearm
                g_sync1  = 0;
            }
        }
    }
}

// ---------------------------------------------------------------------------
// Launch.  Inputs: [0] P f32, [1] index_r i32, [2] sw_abs i32, [3] lw_abs i32.
// ---------------------------------------------------------------------------
extern "C" void kernel_launch(void* const* d_in, const int* in_sizes, int n_in,
                              void* d_out, int out_size) {
    const float4* P4     = (const float4*)d_in[0];
    const float*  Pf     = (const float*)d_in[0];
    const int*    idxr   = (const int*)d_in[1];
    const int*    lw_abs = (const int*)d_in[3];
    float*        out    = (float*)d_out;

    k_all<<<NBLK, 256>>>(P4, Pf, idxr, lw_abs, out);
}

// round 6
// speedup vs baseline: 1.5000x; 1.0309x over previous
#include <cuda_runtime.h>
#include <cuda_bf16.h>
#include <cstdint>

// Problem constants (H=W=256, SMALL=8, LARGE=16, B=2)
#define HW      65536
#define NB      2
#define WNUM    1024
#define S2      64
#define L2      256
#define NTILE   (WNUM*NB)     // 2048
#define NBLK    1024
#define NCORRB  256           // blocks that also do scatter+corr
#define K1      20            // bulk iters for corr blocks
#define K2      36            // bulk iters for plain blocks
// 256*256*K1 + 768*256*K2 = 1310720 + 7077888 = 8388608 float4 = all of P
#define CORR_REGION (NCORRB * 256 * K1)   // 1310720

__device__ int    g_partner[NB * HW];   // 512 KB (L2-resident)
__device__ float2 g_corr[NTILE];        // {nll_sum/c_num, absd_correction}
__device__ float  g_bulk[NBLK];
__device__ int    g_sync1;              // scatter barrier (zero-init, rearmed)
__device__ int    g_ticket;             // completion ticket (zero-init, rearmed)

__device__ __forceinline__ float warp_sum(float v) {
    #pragma unroll
    for (int o = 16; o > 0; o >>= 1) v += __shfl_down_sync(0xFFFFFFFFu, v, o);
    return v;
}

// ---------------------------------------------------------------------------
// Single fused kernel, single wave (occ 7 x 148 SMs >= 1024 blocks).
//  corr blocks (0..255): scatter slice -> K1 bulk iters -> barrier (already
//    drained: scatter finished ~K1 iters ago) -> per-warp tile corrections
//  plain blocks (256..1023): K2 bulk iters
//  last ticket: fixed-order final combine, writes out, rearms counters
// ---------------------------------------------------------------------------
__global__ __launch_bounds__(256, 7)
void k_all(const float4* __restrict__ P4,
           const float*  __restrict__ Pf,
           const int*    __restrict__ index_r,
           const int*    __restrict__ lw_abs,
           float*        __restrict__ out) {
    const int bid  = blockIdx.x;
    const int tid  = threadIdx.x;
    const int lane = tid & 31;
    const int wrp  = tid >> 5;

    float a0 = 0.f, a1 = 0.f;          // bulk accumulators
    float absd = 0.f, nll = 0.f;       // correction accumulators
    float cntf = 0.f;

    if (bid < NCORRB) {
        // ---- scatter slice: 512 entries, coalesced reads, random 4B stores ----
        #pragma unroll
        for (int r = 0; r < 2; r++) {
            int e    = bid * 512 + r * 256 + tid;      // 0..131071
            int b    = e >> 16;
            int j    = e & (HW - 1);
            int idx0 = index_r[(b * 2 + 0) * HW + j];
            int idx1 = index_r[(b * 2 + 1) * HW + j];
            g_partner[b * HW + idx1] = idx0;
        }
        __threadfence();
        __syncthreads();
        if (tid == 0) atomicAdd(&g_sync1, 1);   // arrive early, wait later

        // ---- bulk share (runs while other blocks' scatters finish) ----
        const int base = bid * 256 + tid;       // region [0, CORR_REGION)
        #pragma unroll 4
        for (int k = 0; k < K1; k++) {
            float4 p = __ldcs(P4 + base + k * (NCORRB * 256));
            a0 += p.x + p.y;
            a1 += p.z + p.w;
        }

        // ---- barrier wait (should already be drained) ----
        if (tid == 0) {
            while (*((volatile int*)&g_sync1) < NCORRB) { }
        }
        __syncthreads();
        __threadfence();

        // ---- per-warp tile corrections (tile = bid*8 + warp) ----
        const int tile = bid * 8 + wrp;
        const int w    = tile >> 1;
        const int b    = tile & 1;
        const int r0   = (w >> 5) << 3;
        const int c0   = (w & 31) << 3;
        const float* Pt = Pf + (size_t)tile * (S2 * L2);

        int cnt = 0;
        #pragma unroll
        for (int k = 0; k < 8; k++) {
            int l  = lane + 32 * k;
            int lw = __ldg(lw_abs + w * L2 + l);
            int v  = g_partner[b * HW + lw];             // plw
            int i  = (v >> 8) - r0;
            int j  = (v & 255) - c0;
            if ((unsigned)i < 8u && (unsigned)j < 8u && !(v == 0 && lw == 0)) {
                float p = __ldg(Pt + (i * 8 + j) * L2 + l);
                absd += 1.f - 2.f * p;                   // |p-1| - p
                nll  -= __logf(fminf(fmaxf(p, 1e-6f), 1.f - 1e-6f));
                cnt++;
            }
        }
        cntf = (float)cnt;
        absd = warp_sum(absd);
        nll  = warp_sum(nll);
        cntf = warp_sum(cntf);
        if (lane == 0) g_corr[tile] = make_float2(nll / cntf, absd);
    } else {
        // ---- plain block: bulk only ----
        const int base = CORR_REGION + (bid - NCORRB) * 256 + tid;
        #pragma unroll 4
        for (int k = 0; k < K2; k++) {
            float4 p = __ldcs(P4 + base + k * ((NBLK - NCORRB) * 256));
            a0 += p.x + p.y;
            a1 += p.z + p.w;
        }
    }
    float acc = a0 + a1;

    // ---- block reduction ----
    acc = warp_sum(acc);
    __shared__ float red[8];
    __shared__ bool  s_last;
    if (lane == 0) red[wrp] = acc;
    __syncthreads();
    if (wrp == 0) {
        float a = (lane < 8) ? red[lane] : 0.f;
        #pragma unroll
        for (int o = 4; o > 0; o >>= 1) a += __shfl_down_sync(0xFFFFFFFFu, a, o);
        if (lane == 0) {
            g_bulk[bid] = a;
            __threadfence();
            int t = atomicAdd(&g_ticket, 1);
            s_last = (t == NBLK - 1);
        }
    }
    __syncthreads();

    // ---- final fixed-order combine (deterministic) ----
    if (s_last) {
        float sumP = 0.f, sumC = 0.f, sumR = 0.f;
        #pragma unroll
        for (int i = tid; i < NBLK; i += 256) sumP += g_bulk[i];
        #pragma unroll
        for (int i = tid; i < NTILE; i += 256) {
            float2 v = g_corr[i];
            sumR += v.x;
            sumC += v.y;
        }
        sumP = warp_sum(sumP);
        sumC = warp_sum(sumC);
        sumR = warp_sum(sumR);
        __shared__ float sp[8], sc[8], sr[8];
        if (lane == 0) { sp[wrp] = sumP; sc[wrp] = sumC; sr[wrp] = sumR; }
        __syncthreads();
        if (wrp == 0) {
            float p = (lane < 8) ? sp[lane] : 0.f;
            float c = (lane < 8) ? sc[lane] : 0.f;
            float r = (lane < 8) ? sr[lane] : 0.f;
            #pragma unroll
            for (int o = 4; o > 0; o >>= 1) {
                p += __shfl_down_sync(0xFFFFFFFFu, p, o);
                c += __shfl_down_sync(0xFFFFFFFFu, c, o);
                r += __shfl_down_sync(0xFFFFFFFFu, r, o);
            }
            if (lane == 0) {
                out[0] = r / (float)NTILE;                            // l_cm
                out[1] = (p + c) / (float)((size_t)NTILE * S2 * L2);  // l_c
                g_ticket = 0;                                         // rearm
                g_sync1  = 0;
            }
        }
    }
}

// ---------------------------------------------------------------------------
// Launch.  Inputs: [0] P f32, [1] index_r i32, [2] sw_abs i32, [3] lw_abs i32.
// ---------------------------------------------------------------------------
extern "C" void kernel_launch(void* const* d_in, const int* in_sizes, int n_in,
                              void* d_out, int out_size) {
    const float4* P4     = (const float4*)d_in[0];
    const float*  Pf     = (const float*)d_in[0];
    const int*    idxr   = (const int*)d_in[1];
    const int*    lw_abs = (const int*)d_in[3];
    float*        out    = (float*)d_out;

    k_all<<<NBLK, 256>>>(P4, Pf, idxr, lw_abs, out);
}